// round 3
// baseline (speedup 1.0000x reference)
#include <cuda_runtime.h>
#include <cstdint>

typedef unsigned long long ull;

#define MAXF 20000
#define KK   50          // neighbors kept per face
#define RPB  16          // rows per block
#define NW   8           // warps per block
#define CAP  448         // per-row candidate buffer capacity
#define NBIN 512         // bins = float bits >> 22 (nonneg floats, monotonic)
#define RB   128         // reduce stage-1 blocks

// ---------------- scratch (no allocation allowed) ----------------
__device__ float4 g_cent4[MAXF];                 // x,y,z centroid, w = |c|^2
__device__ float4 g_v0[MAXF], g_v1[MAXF], g_v2[MAXF];
__device__ float4 g_nun[MAXF];                   // unnormalized normal
__device__ float4 g_nrm[MAXF];                   // normalized normal
__device__ int    g_nbr[MAXF * KK];
__device__ float  g_contrib[MAXF];
__device__ double g_partial[RB];

// ---------------- kernel 1: per-face geometry ----------------
__global__ void prep_kernel(const float* __restrict__ verts,
                            const int* __restrict__ faces, int F) {
    int f = blockIdx.x * blockDim.x + threadIdx.x;
    if (f >= F) return;
    int i0 = faces[3 * f + 0], i1 = faces[3 * f + 1], i2 = faces[3 * f + 2];
    float v0x = verts[3 * i0 + 0], v0y = verts[3 * i0 + 1], v0z = verts[3 * i0 + 2];
    float v1x = verts[3 * i1 + 0], v1y = verts[3 * i1 + 1], v1z = verts[3 * i1 + 2];
    float v2x = verts[3 * i2 + 0], v2y = verts[3 * i2 + 1], v2z = verts[3 * i2 + 2];

    float e1x = v1x - v0x, e1y = v1y - v0y, e1z = v1z - v0z;
    float e2x = v2x - v0x, e2y = v2y - v0y, e2z = v2z - v0z;
    float nx = e1y * e2z - e1z * e2y;
    float ny = e1z * e2x - e1x * e2z;
    float nz = e1x * e2y - e1y * e2x;
    float nn = sqrtf(nx * nx + ny * ny + nz * nz) + 1e-8f;

    float cx = (v0x + v1x + v2x) / 3.0f;
    float cy = (v0y + v1y + v2y) / 3.0f;
    float cz = (v0z + v1z + v2z) / 3.0f;
    float sq = cx * cx + cy * cy + cz * cz;

    g_cent4[f] = make_float4(cx, cy, cz, sq);
    g_v0[f]    = make_float4(v0x, v0y, v0z, 0.f);
    g_v1[f]    = make_float4(v1x, v1y, v1z, 0.f);
    g_v2[f]    = make_float4(v2x, v2y, v2z, 0.f);
    g_nun[f]   = make_float4(nx, ny, nz, 0.f);
    g_nrm[f]   = make_float4(nx / nn, ny / nn, nz / nn, 0.f);
}

// ---------------- kernel 2: k-NN, threshold-filtered streaming select ------
__global__ void __launch_bounds__(256, 2) knn_kernel(int F, int kp1) {
    extern __shared__ unsigned char smraw[];
    ull* bufs = (ull*)smraw;                                     // RPB*CAP
    int* hist = (int*)(smraw + (size_t)RPB * CAP * sizeof(ull)); // RPB*NBIN

    __shared__ int      sh_cnt[RPB];
    __shared__ unsigned sh_thr[RPB];

    int tid = threadIdx.x;
    int lane = tid & 31;
    int w = tid >> 5;
    int r0 = blockIdx.x * RPB;

    if (tid < RPB) { sh_cnt[tid] = 0; sh_thr[tid] = 0xFFFFFFFFu; }
    for (int b = tid; b < RPB * NBIN; b += 256) hist[b] = 0;

    float4 cr[RPB];
    #pragma unroll
    for (int r = 0; r < RPB; ++r) {
        int ri = r0 + r;
        cr[r] = g_cent4[ri < F ? ri : 0];
    }

    // ---- phase 1: first `first` candidates inserted directly (no atomics) ----
    int first = F < 128 ? F : 128;
    for (int j = tid; j < first; j += 256) {
        float4 cj = g_cent4[j];
        #pragma unroll
        for (int r = 0; r < RPB; ++r) {
            float dot = cr[r].x * cj.x + cr[r].y * cj.y + cr[r].z * cj.z;
            float d = fmaxf(cr[r].w + cj.w - 2.0f * dot, 0.0f);
            bufs[r * CAP + j] = ((ull)__float_as_uint(d) << 32) | (unsigned)j;
        }
    }
    if (tid < RPB) sh_cnt[tid] = first;

    unsigned thr[RPB];
    int seen = first;
    int chunk = 256;

    for (;;) {
        __syncthreads();
        // ---- per-warp compaction: tighten threshold, filter buffer ----
        for (int rr = w; rr < RPB; rr += NW) {
            ull* bw = bufs + rr * CAP;
            int* h = hist + rr * NBIN;
            int wcnt = sh_cnt[rr]; if (wcnt > CAP) wcnt = CAP;
            if (wcnt >= kp1) {
                for (int e = lane; e < wcnt; e += 32)
                    atomicAdd(&h[(unsigned)(bw[e] >> 54)], 1);   // valbits>>22
                __syncwarp();

                int b0l = lane * 16, s = 0;
                #pragma unroll
                for (int b = 0; b < 16; ++b) s += h[b0l + b];
                int cum = s;
                #pragma unroll
                for (int o = 1; o < 32; o <<= 1) {
                    int t = __shfl_up_sync(0xffffffffu, cum, o);
                    if (lane >= o) cum += t;
                }
                unsigned bal = __ballot_sync(0xffffffffu, cum >= kp1);
                int L = __ffs(bal) - 1;
                int cbef = __shfl_sync(0xffffffffu, cum - s, L);
                int B = 0;
                if (lane == L) {
                    int c = cbef, b = L * 16;
                    for (;; ++b) { c += h[b]; if (c >= kp1) break; }
                    B = b;
                }
                B = __shfl_sync(0xffffffffu, B, L);
                unsigned thrb = ((unsigned)B + 1u) << 22;

                #pragma unroll
                for (int b = 0; b < 16; ++b) h[b0l + b] = 0;     // reset bins

                // in-place forward warp compaction
                int nb = 0;
                for (int i0 = 0; i0 < wcnt; i0 += 32) {
                    int e = i0 + lane;
                    ull v = (e < wcnt) ? bw[e] : ~0ull;
                    bool keep = (e < wcnt) && ((unsigned)(v >> 32) < thrb);
                    unsigned m = __ballot_sync(0xffffffffu, keep);
                    int pos = nb + __popc(m & ((1u << lane) - 1u));
                    __syncwarp();
                    if (keep) bw[pos] = v;
                    nb += __popc(m);
                    __syncwarp();
                }
                if (lane == 0) { sh_cnt[rr] = nb; sh_thr[rr] = thrb; }
            }
        }
        __syncthreads();
        #pragma unroll
        for (int r = 0; r < RPB; ++r) thr[r] = sh_thr[r];

        if (seen >= F) break;
        int jend = seen + chunk; if (jend > F) jend = F;
        chunk <<= 1;

        // ---- hot loop: branch-free compare, one rarely-taken slow path ----
        for (int j = seen + tid; j < jend; j += 256) {
            float4 cj = g_cent4[j];
            bool any = false;
            #pragma unroll
            for (int r = 0; r < RPB; ++r) {
                float dot = cr[r].x * cj.x + cr[r].y * cj.y + cr[r].z * cj.z;
                float d = fmaxf(cr[r].w + cj.w - 2.0f * dot, 0.0f);
                any |= (__float_as_uint(d) < thr[r]);
            }
            if (any) {
                #pragma unroll
                for (int r = 0; r < RPB; ++r) {
                    float dot = cr[r].x * cj.x + cr[r].y * cj.y + cr[r].z * cj.z;
                    float d = fmaxf(cr[r].w + cj.w - 2.0f * dot, 0.0f);
                    unsigned db = __float_as_uint(d);
                    if (db < thr[r]) {
                        int slot = atomicAdd(&sh_cnt[r], 1);
                        if (slot < CAP)
                            bufs[r * CAP + slot] = ((ull)db << 32) | (unsigned)j;
                    }
                }
            }
        }
        seen = jend;
    }

    // ---- final exact selection by rank counting ----
    for (int rr = w; rr < RPB; rr += NW) {
        int ri = r0 + rr;
        if (ri < F) {
            ull* bw = bufs + rr * CAP;
            int wcnt = sh_cnt[rr]; if (wcnt > CAP) wcnt = CAP;
            for (int e = lane; e < wcnt; e += 32) {
                ull ke = bw[e];
                int rank = 0;
                for (int q = 0; q < wcnt; ++q) rank += (bw[q] < ke);
                // rank 0 is the global min (self / lowest-index tie) -> dropped
                if (rank >= 1 && rank < kp1)
                    g_nbr[(size_t)ri * KK + rank - 1] = (int)(unsigned)(ke & 0xffffffffu);
            }
        }
    }
}

// ---------------- kernel 3: collision tests over 50 neighbors ----------------
__global__ void collide_kernel(const int* __restrict__ faces,
                               const float* __restrict__ prob, int F, int kk) {
    int i = blockIdx.x;
    int t = threadIdx.x;
    bool col = false;
    if (t < kk) {
        int j = g_nbr[(size_t)i * KK + t];
        float4 v0i = g_v0[i], v1i = g_v1[i], v2i = g_v2[i];
        float4 ni  = g_nun[i], mi = g_nrm[i], ci = g_cent4[i];
        float4 v0j = g_v0[j], v1j = g_v1[j], v2j = g_v2[j];
        float4 nj  = g_nun[j], mj = g_nrm[j], cj = g_cent4[j];

        float ndot = fabsf(mi.x * mj.x + mi.y * mj.y + mi.z * mj.z);
        bool coplanar = ndot > 0.99f;

        bool inter;
        if (coplanar) {
            float dx = ci.x - cj.x, dy = ci.y - cj.y, dz = ci.z - cj.z;
            inter = sqrtf(dx * dx + dy * dy + dz * dz) < 1e-10f;
        } else {
            float dA0 = (v0j.x - v0i.x) * ni.x + (v0j.y - v0i.y) * ni.y + (v0j.z - v0i.z) * ni.z;
            float dA1 = (v1j.x - v0i.x) * ni.x + (v1j.y - v0i.y) * ni.y + (v1j.z - v0i.z) * ni.z;
            float dA2 = (v2j.x - v0i.x) * ni.x + (v2j.y - v0i.y) * ni.y + (v2j.z - v0i.z) * ni.z;
            bool condA = (dA0 * dA1 <= 0.f) || (dA0 * dA2 <= 0.f) || (dA1 * dA2 <= 0.f);
            float dB0 = (v0i.x - v0j.x) * nj.x + (v0i.y - v0j.y) * nj.y + (v0i.z - v0j.z) * nj.z;
            float dB1 = (v1i.x - v0j.x) * nj.x + (v1i.y - v0j.y) * nj.y + (v1i.z - v0j.z) * nj.z;
            float dB2 = (v2i.x - v0j.x) * nj.x + (v2i.y - v0j.y) * nj.y + (v2i.z - v0j.z) * nj.z;
            bool condB = (dB0 * dB1 <= 0.f) || (dB0 * dB2 <= 0.f) || (dB1 * dB2 <= 0.f);
            inter = condA && condB;
        }

        int a0 = faces[3 * i + 0], a1 = faces[3 * i + 1], a2 = faces[3 * i + 2];
        int b0 = faces[3 * j + 0], b1 = faces[3 * j + 1], b2 = faces[3 * j + 2];
        bool f1 = (a1 != a0);
        bool f2 = (a2 != a0) && (a2 != a1);
        int shared = 0;
        if (a0 == b0 || a0 == b1 || a0 == b2) shared++;
        if (f1 && (a1 == b0 || a1 == b1 || a1 == b2)) shared++;
        if (f2 && (a2 == b0 || a2 == b1 || a2 == b2)) shared++;
        bool adjacent = shared >= 2;

        col = inter && !adjacent;
    }

    unsigned bal = __ballot_sync(0xffffffffu, col);
    __shared__ int wc[2];
    if ((t & 31) == 0) wc[t >> 5] = __popc(bal);
    __syncthreads();
    if (t == 0) g_contrib[i] = prob[i] * (float)(wc[0] + wc[1]);
}

// ---------------- kernels 4/5: deterministic two-stage reduction ------------
__global__ void reduce1_kernel(int F) {
    __shared__ double ps[256];
    int tid = threadIdx.x;
    double s = 0.0;
    for (int i = blockIdx.x * 256 + tid; i < F; i += RB * 256)
        s += (double)g_contrib[i];
    ps[tid] = s;
    __syncthreads();
    for (int o = 128; o; o >>= 1) {
        if (tid < o) ps[tid] += ps[tid + o];
        __syncthreads();
    }
    if (tid == 0) g_partial[blockIdx.x] = ps[0];
}

__global__ void reduce2_kernel(float* __restrict__ out) {
    __shared__ double ps[RB];
    int tid = threadIdx.x;
    ps[tid] = g_partial[tid];
    __syncthreads();
    for (int o = RB / 2; o; o >>= 1) {
        if (tid < o) ps[tid] += ps[tid + o];
        __syncthreads();
    }
    if (tid == 0) out[0] = (float)ps[0];
}

// ---------------- launch ----------------
extern "C" void kernel_launch(void* const* d_in, const int* in_sizes, int n_in,
                              void* d_out, int out_size) {
    const float* verts = (const float*)d_in[0];
    const int*   faces = (const int*)d_in[1];
    const float* prob  = (const float*)d_in[2];
    float* out = (float*)d_out;

    int F = in_sizes[1] / 3;
    if (F > MAXF) F = MAXF;
    int kk = (F - 1 < KK) ? (F - 1) : KK;
    int kp1 = kk + 1;

    prep_kernel<<<(F + 255) / 256, 256>>>(verts, faces, F);

    size_t smem = (size_t)RPB * CAP * sizeof(ull) + (size_t)RPB * NBIN * sizeof(int);
    cudaFuncSetAttribute(knn_kernel, cudaFuncAttributeMaxDynamicSharedMemorySize,
                         (int)smem);
    knn_kernel<<<(F + RPB - 1) / RPB, 256, smem>>>(F, kp1);

    collide_kernel<<<F, 64>>>(faces, prob, F, kk);

    reduce1_kernel<<<RB, 256>>>(F);
    reduce2_kernel<<<1, RB>>>(out);
}

// round 4
// speedup vs baseline: 1.4577x; 1.4577x over previous
#include <cuda_runtime.h>
#include <cstdint>

typedef unsigned long long ull;

#define MAXF 20000
#define KK   50          // neighbors kept per face
#define RPB  8           // rows per block == warps per block
#define CAP  768         // per-row candidate buffer capacity
#define NBIN 512         // bins = float bits >> 22 (nonneg floats, monotonic)
#define RB   128         // reduce stage-1 blocks

// ---------------- scratch (no allocation allowed) ----------------
__device__ float4 g_cent4[MAXF];                 // x,y,z centroid, w = |c|^2
__device__ float4 g_v0[MAXF], g_v1[MAXF], g_v2[MAXF];
__device__ float4 g_nun[MAXF];                   // unnormalized normal
__device__ float4 g_nrm[MAXF];                   // normalized normal
__device__ int    g_nbr[MAXF * KK];
__device__ float  g_contrib[MAXF];
__device__ double g_partial[RB];

// ---------------- kernel 1: per-face geometry ----------------
__global__ void prep_kernel(const float* __restrict__ verts,
                            const int* __restrict__ faces, int F) {
    int f = blockIdx.x * blockDim.x + threadIdx.x;
    if (f >= F) return;
    int i0 = faces[3 * f + 0], i1 = faces[3 * f + 1], i2 = faces[3 * f + 2];
    float v0x = verts[3 * i0 + 0], v0y = verts[3 * i0 + 1], v0z = verts[3 * i0 + 2];
    float v1x = verts[3 * i1 + 0], v1y = verts[3 * i1 + 1], v1z = verts[3 * i1 + 2];
    float v2x = verts[3 * i2 + 0], v2y = verts[3 * i2 + 1], v2z = verts[3 * i2 + 2];

    float e1x = v1x - v0x, e1y = v1y - v0y, e1z = v1z - v0z;
    float e2x = v2x - v0x, e2y = v2y - v0y, e2z = v2z - v0z;
    float nx = e1y * e2z - e1z * e2y;
    float ny = e1z * e2x - e1x * e2z;
    float nz = e1x * e2y - e1y * e2x;
    float nn = sqrtf(nx * nx + ny * ny + nz * nz) + 1e-8f;

    float cx = (v0x + v1x + v2x) / 3.0f;
    float cy = (v0y + v1y + v2y) / 3.0f;
    float cz = (v0z + v1z + v2z) / 3.0f;
    float sq = cx * cx + cy * cy + cz * cz;

    g_cent4[f] = make_float4(cx, cy, cz, sq);
    g_v0[f]    = make_float4(v0x, v0y, v0z, 0.f);
    g_v1[f]    = make_float4(v1x, v1y, v1z, 0.f);
    g_v2[f]    = make_float4(v2x, v2y, v2z, 0.f);
    g_nun[f]   = make_float4(nx, ny, nz, 0.f);
    g_nrm[f]   = make_float4(nx / nn, ny / nn, nz / nn, 0.f);
}

// ---------------- kernel 2: k-NN, threshold-filtered streaming select ------
__global__ void __launch_bounds__(256) knn_kernel(int F, int kp1) {
    extern __shared__ unsigned char smraw[];
    ull* bufs = (ull*)smraw;                                     // RPB*CAP
    int* hist = (int*)(smraw + (size_t)RPB * CAP * sizeof(ull)); // RPB*NBIN

    __shared__ int      sh_cnt[RPB];
    __shared__ unsigned sh_thr[RPB];

    int tid = threadIdx.x;
    int lane = tid & 31;
    int w = tid >> 5;
    int r0 = blockIdx.x * RPB;

    if (tid < RPB) { sh_cnt[tid] = 0; sh_thr[tid] = 0x7F800000u; }  // +inf bits

    float4 cr[RPB];
    #pragma unroll
    for (int r = 0; r < RPB; ++r) {
        int ri = r0 + r;
        cr[r] = g_cent4[ri < F ? ri : 0];
    }

    // ---- phase 1: first `first` candidates written directly (no atomics) ----
    int first = F < 512 ? F : 512;
    for (int j = tid; j < first; j += 256) {
        float4 cj = g_cent4[j];
        #pragma unroll
        for (int r = 0; r < RPB; ++r) {
            float dot = cr[r].x * cj.x + cr[r].y * cj.y + cr[r].z * cj.z;
            float d = fmaxf(cr[r].w + cj.w - 2.0f * dot, 0.0f);
            bufs[r * CAP + j] = ((ull)__float_as_uint(d) << 32) | (unsigned)j;
        }
    }
    if (tid < RPB) sh_cnt[tid] = first;

    float thrf[RPB];
    int seen = first;
    int chunk = 1024;

    for (;;) {
        __syncthreads();
        // ---- compaction: warp w owns row w ----
        {
            ull* bw = bufs + w * CAP;
            int* h = hist + w * NBIN;
            int wcnt = sh_cnt[w]; if (wcnt > CAP) wcnt = CAP;
            if (wcnt >= kp1) {
                for (int b = lane; b < NBIN; b += 32) h[b] = 0;
                __syncwarp();
                for (int e = lane; e < wcnt; e += 32)
                    atomicAdd(&h[(unsigned)(bw[e] >> 54)], 1);   // valbits>>22
                __syncwarp();

                int b0l = lane * 16, s = 0;
                #pragma unroll
                for (int b = 0; b < 16; ++b) s += h[b0l + b];
                int cum = s;
                #pragma unroll
                for (int o = 1; o < 32; o <<= 1) {
                    int t = __shfl_up_sync(0xffffffffu, cum, o);
                    if (lane >= o) cum += t;
                }
                unsigned bal = __ballot_sync(0xffffffffu, cum >= kp1);
                int L = __ffs(bal) - 1;
                int cbef = __shfl_sync(0xffffffffu, cum - s, L);
                int B = 0;
                if (lane == L) {
                    int c = cbef, b = L * 16;
                    for (;; ++b) { c += h[b]; if (c >= kp1) break; }
                    B = b;
                }
                B = __shfl_sync(0xffffffffu, B, L);
                unsigned thrb = ((unsigned)B + 1u) << 22;
                if (thrb > 0x7F800000u) thrb = 0x7F800000u;

                // in-place forward warp compaction
                int nb = 0;
                for (int i0 = 0; i0 < wcnt; i0 += 32) {
                    int e = i0 + lane;
                    ull v = (e < wcnt) ? bw[e] : ~0ull;
                    bool keep = (e < wcnt) && ((unsigned)(v >> 32) < thrb);
                    unsigned m = __ballot_sync(0xffffffffu, keep);
                    int pos = nb + __popc(m & ((1u << lane) - 1u));
                    __syncwarp();
                    if (keep) bw[pos] = v;
                    nb += __popc(m);
                    __syncwarp();
                }
                if (lane == 0) { sh_cnt[w] = nb; sh_thr[w] = thrb; }
            }
        }
        __syncthreads();
        #pragma unroll
        for (int r = 0; r < RPB; ++r) thrf[r] = __uint_as_float(sh_thr[r]);

        if (seen >= F) break;
        int jend = seen + chunk; if (jend > F) jend = F;
        chunk <<= 1;

        // ---- hot loop: 2-wide, branch-free compare, rare out-of-line insert ----
        for (int j0 = seen + tid; j0 < jend; j0 += 512) {
            int j1 = j0 + 256;
            int j1c = j1 < F ? j1 : 0;
            float4 a = g_cent4[j0];
            float4 b = g_cent4[j1c];
            bool hit0 = false, hit1 = false;
            #pragma unroll
            for (int r = 0; r < RPB; ++r) {
                float dota = cr[r].x * a.x + cr[r].y * a.y + cr[r].z * a.z;
                float da = cr[r].w + a.w - 2.0f * dota;
                hit0 |= (da < thrf[r]);
                float dotb = cr[r].x * b.x + cr[r].y * b.y + cr[r].z * b.z;
                float db = cr[r].w + b.w - 2.0f * dotb;
                hit1 |= (db < thrf[r]);
            }
            hit1 = hit1 && (j1 < jend);
            if (hit0 | hit1) {
                #pragma unroll
                for (int r = 0; r < RPB; ++r) {
                    float dota = cr[r].x * a.x + cr[r].y * a.y + cr[r].z * a.z;
                    float da = fmaxf(cr[r].w + a.w - 2.0f * dota, 0.0f);
                    unsigned dba = __float_as_uint(da);
                    if (hit0 && dba < sh_thr[r]) {
                        int slot = atomicAdd(&sh_cnt[r], 1);
                        if (slot < CAP)
                            bufs[r * CAP + slot] = ((ull)dba << 32) | (unsigned)j0;
                    }
                    float dotb = cr[r].x * b.x + cr[r].y * b.y + cr[r].z * b.z;
                    float db = fmaxf(cr[r].w + b.w - 2.0f * dotb, 0.0f);
                    unsigned dbb = __float_as_uint(db);
                    if (hit1 && dbb < sh_thr[r]) {
                        int slot = atomicAdd(&sh_cnt[r], 1);
                        if (slot < CAP)
                            bufs[r * CAP + slot] = ((ull)dbb << 32) | (unsigned)j1;
                    }
                }
            }
        }
        seen = jend;
    }

    // ---- final exact selection by rank counting (warp w -> row w) ----
    {
        int ri = r0 + w;
        if (ri < F) {
            ull* bw = bufs + w * CAP;
            int wcnt = sh_cnt[w]; if (wcnt > CAP) wcnt = CAP;
            for (int e = lane; e < wcnt; e += 32) {
                ull ke = bw[e];
                int rank = 0;
                for (int q = 0; q < wcnt; ++q) rank += (bw[q] < ke);
                // rank 0 is the global min (self / lowest-index tie) -> dropped
                if (rank >= 1 && rank < kp1)
                    g_nbr[(size_t)ri * KK + rank - 1] = (int)(unsigned)(ke & 0xffffffffu);
            }
        }
    }
}

// ---------------- kernel 3: collision tests, 4 faces per block --------------
__global__ void __launch_bounds__(256) collide_kernel(const int* __restrict__ faces,
                               const float* __restrict__ prob, int F, int kk) {
    int f = blockIdx.x * 4 + (threadIdx.x >> 6);
    int t = threadIdx.x & 63;
    bool col = false;
    if (f < F && t < kk) {
        int i = f;
        int j = g_nbr[(size_t)i * KK + t];
        float4 v0i = g_v0[i], v1i = g_v1[i], v2i = g_v2[i];
        float4 ni  = g_nun[i], mi = g_nrm[i], ci = g_cent4[i];
        float4 v0j = g_v0[j], v1j = g_v1[j], v2j = g_v2[j];
        float4 nj  = g_nun[j], mj = g_nrm[j], cj = g_cent4[j];

        float ndot = fabsf(mi.x * mj.x + mi.y * mj.y + mi.z * mj.z);
        bool coplanar = ndot > 0.99f;

        bool inter;
        if (coplanar) {
            float dx = ci.x - cj.x, dy = ci.y - cj.y, dz = ci.z - cj.z;
            inter = sqrtf(dx * dx + dy * dy + dz * dz) < 1e-10f;
        } else {
            float dA0 = (v0j.x - v0i.x) * ni.x + (v0j.y - v0i.y) * ni.y + (v0j.z - v0i.z) * ni.z;
            float dA1 = (v1j.x - v0i.x) * ni.x + (v1j.y - v0i.y) * ni.y + (v1j.z - v0i.z) * ni.z;
            float dA2 = (v2j.x - v0i.x) * ni.x + (v2j.y - v0i.y) * ni.y + (v2j.z - v0i.z) * ni.z;
            bool condA = (dA0 * dA1 <= 0.f) || (dA0 * dA2 <= 0.f) || (dA1 * dA2 <= 0.f);
            float dB0 = (v0i.x - v0j.x) * nj.x + (v0i.y - v0j.y) * nj.y + (v0i.z - v0j.z) * nj.z;
            float dB1 = (v1i.x - v0j.x) * nj.x + (v1i.y - v0j.y) * nj.y + (v1i.z - v0j.z) * nj.z;
            float dB2 = (v2i.x - v0j.x) * nj.x + (v2i.y - v0j.y) * nj.y + (v2i.z - v0j.z) * nj.z;
            bool condB = (dB0 * dB1 <= 0.f) || (dB0 * dB2 <= 0.f) || (dB1 * dB2 <= 0.f);
            inter = condA && condB;
        }

        int a0 = faces[3 * i + 0], a1 = faces[3 * i + 1], a2 = faces[3 * i + 2];
        int b0 = faces[3 * j + 0], b1 = faces[3 * j + 1], b2 = faces[3 * j + 2];
        bool f1 = (a1 != a0);
        bool f2 = (a2 != a0) && (a2 != a1);
        int shared = 0;
        if (a0 == b0 || a0 == b1 || a0 == b2) shared++;
        if (f1 && (a1 == b0 || a1 == b1 || a1 == b2)) shared++;
        if (f2 && (a2 == b0 || a2 == b1 || a2 == b2)) shared++;
        bool adjacent = shared >= 2;

        col = inter && !adjacent;
    }

    unsigned bal = __ballot_sync(0xffffffffu, col);
    __shared__ int wc[8];
    if ((threadIdx.x & 31) == 0) wc[threadIdx.x >> 5] = __popc(bal);
    __syncthreads();
    if (threadIdx.x < 4) {
        int f2 = blockIdx.x * 4 + threadIdx.x;
        if (f2 < F)
            g_contrib[f2] = prob[f2] * (float)(wc[2 * threadIdx.x] + wc[2 * threadIdx.x + 1]);
    }
}

// ---------------- kernels 4/5: deterministic two-stage reduction ------------
__global__ void reduce1_kernel(int F) {
    __shared__ double ps[256];
    int tid = threadIdx.x;
    double s = 0.0;
    for (int i = blockIdx.x * 256 + tid; i < F; i += RB * 256)
        s += (double)g_contrib[i];
    ps[tid] = s;
    __syncthreads();
    for (int o = 128; o; o >>= 1) {
        if (tid < o) ps[tid] += ps[tid + o];
        __syncthreads();
    }
    if (tid == 0) g_partial[blockIdx.x] = ps[0];
}

__global__ void reduce2_kernel(float* __restrict__ out) {
    __shared__ double ps[RB];
    int tid = threadIdx.x;
    ps[tid] = g_partial[tid];
    __syncthreads();
    for (int o = RB / 2; o; o >>= 1) {
        if (tid < o) ps[tid] += ps[tid + o];
        __syncthreads();
    }
    if (tid == 0) out[0] = (float)ps[0];
}

// ---------------- launch ----------------
extern "C" void kernel_launch(void* const* d_in, const int* in_sizes, int n_in,
                              void* d_out, int out_size) {
    const float* verts = (const float*)d_in[0];
    const int*   faces = (const int*)d_in[1];
    const float* prob  = (const float*)d_in[2];
    float* out = (float*)d_out;

    int F = in_sizes[1] / 3;
    if (F > MAXF) F = MAXF;
    int kk = (F - 1 < KK) ? (F - 1) : KK;
    int kp1 = kk + 1;

    prep_kernel<<<(F + 255) / 256, 256>>>(verts, faces, F);

    size_t smem = (size_t)RPB * CAP * sizeof(ull) + (size_t)RPB * NBIN * sizeof(int);
    cudaFuncSetAttribute(knn_kernel, cudaFuncAttributeMaxDynamicSharedMemorySize,
                         (int)smem);
    knn_kernel<<<(F + RPB - 1) / RPB, 256, smem>>>(F, kp1);

    collide_kernel<<<(F + 3) / 4, 256>>>(faces, prob, F, kk);

    reduce1_kernel<<<RB, 256>>>(F);
    reduce2_kernel<<<1, RB>>>(out);
}